// round 6
// baseline (speedup 1.0000x reference)
#include <cuda_runtime.h>
#include <cuda_bf16.h>

// Shapes (fixed by the problem)
#define B_  16
#define N_  1024
#define L_  7
#define D_  512
#define H_  8
#define HD_ 64
#define BN_ (B_ * N_)   // 16384

// ---------------- scratch (device globals; no cudaMalloc allowed) ----------
__device__ __align__(16) float g_agg[BN_ * D_];
__device__ __align__(16) float g_Qb [BN_ * D_];
__device__ __align__(16) float g_Kb [BN_ * D_];
__device__ __align__(16) float g_Vb [BN_ * D_];
__device__ __align__(16) float g_att[BN_ * D_];
__device__ __align__(16) float g_Ob [BN_ * D_];

// ---------------- packed fp32x2 helpers (Blackwell; ptxas never emits these)
__device__ __forceinline__ void fma2(unsigned long long& d,
                                     unsigned long long a,
                                     unsigned long long b) {
    asm("fma.rn.f32x2 %0, %1, %2, %0;" : "+l"(d) : "l"(a), "l"(b));
}
__device__ __forceinline__ void mul2(unsigned long long& d, unsigned long long a) {
    asm("mul.rn.f32x2 %0, %0, %1;" : "+l"(d) : "l"(a));
}
__device__ __forceinline__ unsigned long long bcast2f(float x) {
    unsigned long long r;
    asm("mov.b64 %0, {%1, %1};" : "=l"(r) : "f"(x));
    return r;
}
__device__ __forceinline__ unsigned long long pack2f(float x, float y) {
    unsigned long long r;
    asm("mov.b64 %0, {%1, %2};" : "=l"(r) : "f"(x), "f"(y));
    return r;
}
__device__ __forceinline__ float2 unpack2(unsigned long long v) {
    float2 r;
    asm("mov.b64 {%0, %1}, %2;" : "=f"(r.x), "=f"(r.y) : "l"(v));
    return r;
}

// ---------------- warp reductions ------------------------------------------
__device__ __forceinline__ float warpMax(float v) {
#pragma unroll
    for (int o = 16; o > 0; o >>= 1) v = fmaxf(v, __shfl_xor_sync(0xffffffffu, v, o));
    return v;
}
__device__ __forceinline__ float warpSum(float v) {
#pragma unroll
    for (int o = 16; o > 0; o >>= 1) v += __shfl_xor_sync(0xffffffffu, v, o);
    return v;
}

// ---------------- Kernel 1: lag softmax + aggregation ----------------------
__global__ void __launch_bounds__(256)
lag_agg_kernel(const float* __restrict__ lf, const float* __restrict__ lw,
               float* __restrict__ outp)
{
    float wv[L_];
    float mx = lw[0];
#pragma unroll
    for (int l = 1; l < L_; l++) mx = fmaxf(mx, lw[l]);
    float sm = 0.f;
#pragma unroll
    for (int l = 0; l < L_; l++) { wv[l] = __expf(lw[l] - mx); sm += wv[l]; }
    float inv = 1.f / sm;
#pragma unroll
    for (int l = 0; l < L_; l++) wv[l] *= inv;

    int idx = blockIdx.x * 256 + threadIdx.x;        // float4 index
    int bn  = idx >> 7;
    int d4  = (idx & 127) * 4;
    const float* base = lf + (long)bn * (L_ * D_) + d4;
    float4 acc = make_float4(0.f, 0.f, 0.f, 0.f);
#pragma unroll
    for (int l = 0; l < L_; l++) {
        float4 v = *(const float4*)(base + l * D_);
        acc.x = fmaf(wv[l], v.x, acc.x);
        acc.y = fmaf(wv[l], v.y, acc.y);
        acc.z = fmaf(wv[l], v.z, acc.z);
        acc.w = fmaf(wv[l], v.w, acc.w);
    }
    *(float4*)(outp + (long)bn * D_ + d4) = acc;
}

// ---------------- Kernel 2: GEMM  C = A @ W^T + bias -----------------------
// 128x128x16 tile, 256 threads, 8x8 microtile, FFMA2-packed along n,
// register double-buffered global->shared staging. (unchanged from R5)
__global__ void __launch_bounds__(256)
gemm_bias_kernel(const float* __restrict__ A, const float* __restrict__ W,
                 const float* __restrict__ bias, float* __restrict__ C)
{
    __shared__ __align__(16) float As[16][132];
    __shared__ __align__(16) float Ws[16][132];

    const int tid = threadIdx.x;
    const int tx = tid & 15, ty = tid >> 4;
    const int row0 = blockIdx.y << 7;
    const int col0 = blockIdx.x << 7;

    const int r_st0 = tid >> 2,         kq_st0 = (tid & 3) * 4;
    const int r_st1 = (tid + 256) >> 2, kq_st1 = ((tid + 256) & 3) * 4;

    unsigned long long acc2[8][4];
#pragma unroll
    for (int j = 0; j < 8; j++)
#pragma unroll
        for (int i = 0; i < 4; i++) acc2[j][i] = 0ull;

    float4 aR0 = *(const float4*)(A + (long)(row0 + r_st0) * D_ + kq_st0);
    float4 wR0 = *(const float4*)(W + (long)(col0 + r_st0) * D_ + kq_st0);
    float4 aR1 = *(const float4*)(A + (long)(row0 + r_st1) * D_ + kq_st1);
    float4 wR1 = *(const float4*)(W + (long)(col0 + r_st1) * D_ + kq_st1);

    for (int k0 = 0; k0 < D_; k0 += 16) {
        As[kq_st0 + 0][r_st0] = aR0.x; As[kq_st0 + 1][r_st0] = aR0.y;
        As[kq_st0 + 2][r_st0] = aR0.z; As[kq_st0 + 3][r_st0] = aR0.w;
        Ws[kq_st0 + 0][r_st0] = wR0.x; Ws[kq_st0 + 1][r_st0] = wR0.y;
        Ws[kq_st0 + 2][r_st0] = wR0.z; Ws[kq_st0 + 3][r_st0] = wR0.w;
        As[kq_st1 + 0][r_st1] = aR1.x; As[kq_st1 + 1][r_st1] = aR1.y;
        As[kq_st1 + 2][r_st1] = aR1.z; As[kq_st1 + 3][r_st1] = aR1.w;
        Ws[kq_st1 + 0][r_st1] = wR1.x; Ws[kq_st1 + 1][r_st1] = wR1.y;
        Ws[kq_st1 + 2][r_st1] = wR1.z; Ws[kq_st1 + 3][r_st1] = wR1.w;
        __syncthreads();

        if (k0 + 16 < D_) {
            int kn = k0 + 16;
            aR0 = *(const float4*)(A + (long)(row0 + r_st0) * D_ + kn + kq_st0);
            wR0 = *(const float4*)(W + (long)(col0 + r_st0) * D_ + kn + kq_st0);
            aR1 = *(const float4*)(A + (long)(row0 + r_st1) * D_ + kn + kq_st1);
            wR1 = *(const float4*)(W + (long)(col0 + r_st1) * D_ + kn + kq_st1);
        }

#pragma unroll
        for (int k = 0; k < 16; k++) {
            float a[8];
            *(float4*)&a[0] = *(const float4*)&As[k][ty * 8];
            *(float4*)&a[4] = *(const float4*)&As[k][ty * 8 + 4];
            ulonglong2 b01 = *(const ulonglong2*)&Ws[k][tx * 8];
            ulonglong2 b23 = *(const ulonglong2*)&Ws[k][tx * 8 + 4];
            unsigned long long b2[4] = {b01.x, b01.y, b23.x, b23.y};
#pragma unroll
            for (int j = 0; j < 8; j++) {
                unsigned long long aj = bcast2f(a[j]);
                fma2(acc2[j][0], aj, b2[0]);
                fma2(acc2[j][1], aj, b2[1]);
                fma2(acc2[j][2], aj, b2[2]);
                fma2(acc2[j][3], aj, b2[3]);
            }
        }
        __syncthreads();
    }

    float bv[8];
    *(float4*)&bv[0] = *(const float4*)(bias + col0 + tx * 8);
    *(float4*)&bv[4] = *(const float4*)(bias + col0 + tx * 8 + 4);
#pragma unroll
    for (int j = 0; j < 8; j++) {
        int row = row0 + ty * 8 + j;
        float2 c0 = unpack2(acc2[j][0]);
        float2 c1 = unpack2(acc2[j][1]);
        float2 c2 = unpack2(acc2[j][2]);
        float2 c3 = unpack2(acc2[j][3]);
        float4 r0 = make_float4(c0.x + bv[0], c0.y + bv[1],
                                c1.x + bv[2], c1.y + bv[3]);
        float4 r1 = make_float4(c2.x + bv[4], c2.y + bv[5],
                                c3.x + bv[6], c3.y + bv[7]);
        *(float4*)(C + (long)row * D_ + col0 + tx * 8)     = r0;
        *(float4*)(C + (long)row * D_ + col0 + tx * 8 + 4) = r1;
    }
}

// ---------------- Kernel 3: flash attention, row-pair f32x2 packing --------
// grid: (N/32, B*H). block: 256 threads (8 warps).
// Warp w owns q-rows 4w..4w+3 as two row-pairs (4w,4w+1), (4w+2,4w+3).
// Lane l owns kv cols (2l, 2l+1) for scores and out dims (2l, 2l+1).
// Accumulators are packed over the ROW pair, so the Q / P operand pair comes
// straight from shared (transposed staging, lane-uniform LDS.128) and each
// K / V scalar broadcast is reused across both row-pairs.
__global__ void __launch_bounds__(256)
attn_kernel(const float* __restrict__ Qg, const float* __restrict__ Kg,
            const float* __restrict__ Vg, const float* __restrict__ adj,
            float* __restrict__ Og)
{
    __shared__ __align__(16) float Qt[64 * 36];   // Qt[d][r], stride 36 (LDS.128-aligned for all d)
    __shared__ __align__(16) float KtPs[64 * 66]; // Kt[d][c] stride 66; overlaid by Ps[c][r] stride 36
    __shared__ __align__(16) float Vs[64 * 64];   // V[c][d], stride 64

    const int tid = threadIdx.x;
    const int w = tid >> 5, l = tid & 31;
    const int bh = blockIdx.y;
    const int b = bh >> 3, h = bh & 7;
    const int q0 = blockIdx.x * 32;

    const float* Qbase = Qg + ((long)(b * N_ + q0) * D_) + h * HD_;
    // stage Q transposed + scaled: Qt[d][r] = 0.125 * Q[r][d]
#pragma unroll
    for (int j = 0; j < 2; j++) {
        int fi = tid + j * 256;          // 0..511 = 32 rows x 16 float4
        int r = fi >> 4, f4 = (fi & 15) * 4;
        float4 q = *(const float4*)(Qbase + (long)r * D_ + f4);
        Qt[(f4 + 0) * 36 + r] = q.x * 0.125f;
        Qt[(f4 + 1) * 36 + r] = q.y * 0.125f;
        Qt[(f4 + 2) * 36 + r] = q.z * 0.125f;
        Qt[(f4 + 3) * 36 + r] = q.w * 0.125f;
    }

    // o2[p][dd] = {o[4w+2p][2l+dd], o[4w+2p+1][2l+dd]}
    unsigned long long o2[2][2] = {{0ull, 0ull}, {0ull, 0ull}};
    float mrow[4] = {-1e30f, -1e30f, -1e30f, -1e30f};
    float lsum[4] = {0.f, 0.f, 0.f, 0.f};

    for (int t = 0; t < 16; t++) {
        const int c0 = t * 64;
        __syncthreads();   // prev tile PV done (and Qt staged on first iter)

        const float* Kbase = Kg + ((long)(b * N_ + c0) * D_) + h * HD_;
        const float* Vbase = Vg + ((long)(b * N_ + c0) * D_) + h * HD_;
#pragma unroll
        for (int j = 0; j < 4; j++) {
            int fi = tid + j * 256;      // 0..1023 = 64 rows x 16 float4
            int c = fi >> 4, f4 = (fi & 15) * 4;
            float4 kv = *(const float4*)(Kbase + (long)c * D_ + f4);
            KtPs[(f4 + 0) * 66 + c] = kv.x;
            KtPs[(f4 + 1) * 66 + c] = kv.y;
            KtPs[(f4 + 2) * 66 + c] = kv.z;
            KtPs[(f4 + 3) * 66 + c] = kv.w;
            float4 vv = *(const float4*)(Vbase + (long)c * D_ + f4);
            *(float4*)&Vs[c * 64 + f4] = vv;
        }
        __syncthreads();

        // adjacency bias prefetch (L2-resident)
        float2 ad[4];
#pragma unroll
        for (int r = 0; r < 4; r++)
            ad[r] = *(const float2*)(adj + (long)(q0 + 4 * w + r) * N_ + c0 + 2 * l);

        // QK^T: s2[p][cc] = {s[4w+2p][2l+cc], s[4w+2p+1][2l+cc]}
        unsigned long long s2[2][2] = {{0ull, 0ull}, {0ull, 0ull}};
#pragma unroll
        for (int d = 0; d < 64; d++) {
            // both row-pairs in one lane-uniform LDS.128 (broadcast)
            ulonglong2 qp = *(const ulonglong2*)&Qt[d * 36 + 4 * w];
            float2 kk = *(const float2*)&KtPs[d * 66 + 2 * l];
            unsigned long long k0 = bcast2f(kk.x);
            unsigned long long k1 = bcast2f(kk.y);
            fma2(s2[0][0], qp.x, k0); fma2(s2[0][1], qp.x, k1);
            fma2(s2[1][0], qp.y, k0); fma2(s2[1][1], qp.y, k1);
        }
        __syncthreads();   // all warps done reading Kt before Ps overlays it

        // unpack scores: rows r=0..3 <-> 4w+r
        float2 sA0 = unpack2(s2[0][0]);   // {row0 c0, row1 c0}
        float2 sB0 = unpack2(s2[0][1]);   // {row0 c1, row1 c1}
        float2 sA1 = unpack2(s2[1][0]);
        float2 sB1 = unpack2(s2[1][1]);
        float sc0[4] = {sA0.x, sA0.y, sA1.x, sA1.y};
        float sc1[4] = {sB0.x, sB0.y, sB1.x, sB1.y};
        float alv[4], pr0[4], pr1[4];
#pragma unroll
        for (int r = 0; r < 4; r++) {
            float v0 = fmaf(ad[r].x, 0.5f, sc0[r]);
            float v1 = fmaf(ad[r].y, 0.5f, sc1[r]);
            float mx = warpMax(fmaxf(v0, v1));
            float mn = fmaxf(mrow[r], mx);
            float al = __expf(mrow[r] - mn);
            mrow[r] = mn;
            float p0 = __expf(v0 - mn);
            float p1 = __expf(v1 - mn);
            float ps = warpSum(p0 + p1);
            lsum[r] = lsum[r] * al + ps;
            alv[r] = al; pr0[r] = p0; pr1[r] = p1;
        }
        // rescale packed outputs: pair p scales by {alv[2p], alv[2p+1]}
        {
            unsigned long long a0 = pack2f(alv[0], alv[1]);
            unsigned long long a1 = pack2f(alv[2], alv[3]);
            mul2(o2[0][0], a0); mul2(o2[0][1], a0);
            mul2(o2[1][0], a1); mul2(o2[1][1], a1);
        }
        // stage probabilities transposed: Ps[c][r] (stride 36, overlaying Kt)
        *(float2*)&KtPs[(2 * l) * 36 + 4 * w]         = make_float2(pr0[0], pr0[1]);
        *(float2*)&KtPs[(2 * l) * 36 + 4 * w + 2]     = make_float2(pr0[2], pr0[3]);
        *(float2*)&KtPs[(2 * l + 1) * 36 + 4 * w]     = make_float2(pr1[0], pr1[1]);
        *(float2*)&KtPs[(2 * l + 1) * 36 + 4 * w + 2] = make_float2(pr1[2], pr1[3]);
        __syncwarp();      // own warp's Ps rows visible (only warp w reads rows 4w..4w+3)

        // PV: o2[p][dd] += {p[re][c], p[ro][c]} * V[c][2l+dd]
#pragma unroll
        for (int c = 0; c < 64; c++) {
            ulonglong2 pp = *(const ulonglong2*)&KtPs[c * 36 + 4 * w];  // lane-uniform
            float2 vv = *(const float2*)&Vs[c * 64 + 2 * l];
            unsigned long long v0 = bcast2f(vv.x);
            unsigned long long v1 = bcast2f(vv.y);
            fma2(o2[0][0], pp.x, v0); fma2(o2[0][1], pp.x, v1);
            fma2(o2[1][0], pp.y, v0); fma2(o2[1][1], pp.y, v1);
        }
    }

    // epilogue: unpack row pairs, normalize, store
#pragma unroll
    for (int p = 0; p < 2; p++) {
        float2 oa = unpack2(o2[p][0]);   // {o[re][2l],   o[ro][2l]}
        float2 ob = unpack2(o2[p][1]);   // {o[re][2l+1], o[ro][2l+1]}
        float inv_e = 1.f / lsum[2 * p];
        float inv_o = 1.f / lsum[2 * p + 1];
        int re = q0 + 4 * w + 2 * p;
        *(float2*)(Og + ((long)(b * N_ + re) * D_) + h * HD_ + 2 * l)
            = make_float2(oa.x * inv_e, ob.x * inv_e);
        *(float2*)(Og + ((long)(b * N_ + re + 1) * D_) + h * HD_ + 2 * l)
            = make_float2(oa.y * inv_o, ob.y * inv_o);
    }
}

// ---------------- Kernel 4: residual + LayerNorm ---------------------------
__global__ void __launch_bounds__(128)
ln_kernel(const float* __restrict__ cur, const float* __restrict__ O,
          const float* __restrict__ gg, const float* __restrict__ bb,
          float* __restrict__ outp)
{
    __shared__ float red[8];
    const int row = blockIdx.x;
    const int t = threadIdx.x;
    const long base = (long)row * D_ + t * 4;

    float4 c4 = *(const float4*)(cur + base);
    float4 o4 = *(const float4*)(O + base);
    float4 x = make_float4(c4.x + o4.x, c4.y + o4.y, c4.z + o4.z, c4.w + o4.w);

    float s = x.x + x.y + x.z + x.w;
    float q = x.x * x.x + x.y * x.y + x.z * x.z + x.w * x.w;
    s = warpSum(s);
    q = warpSum(q);
    int wid = t >> 5;
    if ((t & 31) == 0) { red[wid] = s; red[4 + wid] = q; }
    __syncthreads();
    s = red[0] + red[1] + red[2] + red[3];
    q = red[4] + red[5] + red[6] + red[7];

    float mu = s * (1.f / D_);
    float var = q * (1.f / D_) - mu * mu;
    float rs = rsqrtf(var + 1e-5f);

    float4 g4 = *(const float4*)(gg + t * 4);
    float4 b4 = *(const float4*)(bb + t * 4);
    float4 y;
    y.x = (x.x - mu) * rs * g4.x + b4.x;
    y.y = (x.y - mu) * rs * g4.y + b4.y;
    y.z = (x.z - mu) * rs * g4.z + b4.z;
    y.w = (x.w - mu) * rs * g4.w + b4.w;
    *(float4*)(outp + base) = y;
}

// ---------------- launcher -------------------------------------------------
extern "C" void kernel_launch(void* const* d_in, const int* in_sizes, int n_in,
                              void* d_out, int out_size)
{
    const float* cur  = (const float*)d_in[0];
    const float* lf   = (const float*)d_in[1];
    const float* lw   = (const float*)d_in[2];
    const float* Wq   = (const float*)d_in[3];
    const float* bq   = (const float*)d_in[4];
    const float* Wk   = (const float*)d_in[5];
    const float* bk   = (const float*)d_in[6];
    const float* Wv   = (const float*)d_in[7];
    const float* bv   = (const float*)d_in[8];
    const float* Wo   = (const float*)d_in[9];
    const float* bo   = (const float*)d_in[10];
    const float* adj  = (const float*)d_in[11];
    const float* lng  = (const float*)d_in[12];
    const float* lnb  = (const float*)d_in[13];
    float* outp = (float*)d_out;

    float *agg, *Qb, *Kb, *Vb, *Ab, *Ob;
    cudaGetSymbolAddress((void**)&agg, g_agg);
    cudaGetSymbolAddress((void**)&Qb,  g_Qb);
    cudaGetSymbolAddress((void**)&Kb,  g_Kb);
    cudaGetSymbolAddress((void**)&Vb,  g_Vb);
    cudaGetSymbolAddress((void**)&Ab,  g_att);
    cudaGetSymbolAddress((void**)&Ob,  g_Ob);

    // 1) lag-weighted aggregation
    lag_agg_kernel<<<(BN_ * D_ / 4) / 256, 256>>>(lf, lw, agg);

    // 2) Q,K,V projections
    dim3 ggrid(D_ / 128, BN_ / 128);
    gemm_bias_kernel<<<ggrid, 256>>>(cur, Wq, bq, Qb);
    gemm_bias_kernel<<<ggrid, 256>>>(agg, Wk, bk, Kb);
    gemm_bias_kernel<<<ggrid, 256>>>(agg, Wv, bv, Vb);

    // 3) attention with adjacency bias
    dim3 agrid(N_ / 32, B_ * H_);
    attn_kernel<<<agrid, 256>>>(Qb, Kb, Vb, adj, Ab);

    // 4) output projection
    gemm_bias_kernel<<<ggrid, 256>>>(Ab, Wo, bo, Ob);

    // 5) residual + layernorm
    ln_kernel<<<BN_, 128>>>(cur, Ob, lng, lnb, outp);
}

// round 13
// speedup vs baseline: 1.1828x; 1.1828x over previous
#include <cuda_runtime.h>
#include <cuda_bf16.h>

// Shapes (fixed by the problem)
#define B_  16
#define N_  1024
#define L_  7
#define D_  512
#define H_  8
#define HD_ 64
#define BN_ (B_ * N_)   // 16384

// attention tiling
#define QR_   64        // q rows per block
#define QSTR  68        // Qt row stride (floats); 272B => LDS.128-aligned for all d
#define KSTR  66        // Kt row stride
#define PSTR  68        // Ps row stride; 272B => LDS.128-aligned
#define ATTN_SMEM_FLOATS (64 * QSTR + 64 * PSTR + 64 * 64)   // Qt + (Kt|Ps union) + Vs = 12800
#define ATTN_SMEM_BYTES  (ATTN_SMEM_FLOATS * 4)              // 51200

// ---------------- scratch (device globals; no cudaMalloc allowed) ----------
__device__ __align__(16) float g_agg[BN_ * D_];
__device__ __align__(16) float g_Qb [BN_ * D_];
__device__ __align__(16) float g_Kb [BN_ * D_];
__device__ __align__(16) float g_Vb [BN_ * D_];
__device__ __align__(16) float g_att[BN_ * D_];
__device__ __align__(16) float g_Ob [BN_ * D_];

// ---------------- packed fp32x2 helpers ------------------------------------
__device__ __forceinline__ void fma2(unsigned long long& d,
                                     unsigned long long a,
                                     unsigned long long b) {
    asm("fma.rn.f32x2 %0, %1, %2, %0;" : "+l"(d) : "l"(a), "l"(b));
}
__device__ __forceinline__ void mul2(unsigned long long& d, unsigned long long a) {
    asm("mul.rn.f32x2 %0, %0, %1;" : "+l"(d) : "l"(a));
}
__device__ __forceinline__ unsigned long long bcast2f(float x) {
    unsigned long long r;
    asm("mov.b64 %0, {%1, %1};" : "=l"(r) : "f"(x));
    return r;
}
__device__ __forceinline__ unsigned long long pack2f(float x, float y) {
    unsigned long long r;
    asm("mov.b64 %0, {%1, %2};" : "=l"(r) : "f"(x), "f"(y));
    return r;
}
__device__ __forceinline__ float2 unpack2(unsigned long long v) {
    float2 r;
    asm("mov.b64 {%0, %1}, %2;" : "=f"(r.x), "=f"(r.y) : "l"(v));
    return r;
}

// ---------------- warp reductions ------------------------------------------
__device__ __forceinline__ float warpMax(float v) {
#pragma unroll
    for (int o = 16; o > 0; o >>= 1) v = fmaxf(v, __shfl_xor_sync(0xffffffffu, v, o));
    return v;
}
__device__ __forceinline__ float warpSum(float v) {
#pragma unroll
    for (int o = 16; o > 0; o >>= 1) v += __shfl_xor_sync(0xffffffffu, v, o);
    return v;
}

// ---------------- Kernel 1: lag softmax + aggregation ----------------------
__global__ void __launch_bounds__(256)
lag_agg_kernel(const float* __restrict__ lf, const float* __restrict__ lw,
               float* __restrict__ outp)
{
    float wv[L_];
    float mx = lw[0];
#pragma unroll
    for (int l = 1; l < L_; l++) mx = fmaxf(mx, lw[l]);
    float sm = 0.f;
#pragma unroll
    for (int l = 0; l < L_; l++) { wv[l] = __expf(lw[l] - mx); sm += wv[l]; }
    float inv = 1.f / sm;
#pragma unroll
    for (int l = 0; l < L_; l++) wv[l] *= inv;

    int idx = blockIdx.x * 256 + threadIdx.x;
    int bn  = idx >> 7;
    int d4  = (idx & 127) * 4;
    const float* base = lf + (long)bn * (L_ * D_) + d4;
    float4 acc = make_float4(0.f, 0.f, 0.f, 0.f);
#pragma unroll
    for (int l = 0; l < L_; l++) {
        float4 v = *(const float4*)(base + l * D_);
        acc.x = fmaf(wv[l], v.x, acc.x);
        acc.y = fmaf(wv[l], v.y, acc.y);
        acc.z = fmaf(wv[l], v.z, acc.z);
        acc.w = fmaf(wv[l], v.w, acc.w);
    }
    *(float4*)(outp + (long)bn * D_ + d4) = acc;
}

// ---------------- GEMM body: C = A @ W^T + bias ----------------------------
// 128x128x16 tile, 256 threads, 8x8 microtile, FFMA2-packed along n.
// 2-stage double-buffered smem: ONE __syncthreads per k-tile; LDG of tile t+2
// issued before the compute block so its latency hides under 16 k-steps of FMA.
__device__ __forceinline__ void
gemm_body(const float* __restrict__ A, const float* __restrict__ W,
          const float* __restrict__ bias, float* __restrict__ C,
          int row0, int col0)
{
    __shared__ __align__(16) float As[2][16][132];
    __shared__ __align__(16) float Ws[2][16][132];

    const int tid = threadIdx.x;
    const int tx = tid & 15, ty = tid >> 4;

    const int r_st0 = tid >> 2,         kq_st0 = (tid & 3) * 4;
    const int r_st1 = (tid + 256) >> 2, kq_st1 = ((tid + 256) & 3) * 4;

    unsigned long long acc2[8][4];
#pragma unroll
    for (int j = 0; j < 8; j++)
#pragma unroll
        for (int i = 0; i < 4; i++) acc2[j][i] = 0ull;

    // prologue: tile 0 -> regs -> buf0 ; tile 1 -> regs
    float4 aR0 = *(const float4*)(A + (long)(row0 + r_st0) * D_ + kq_st0);
    float4 wR0 = *(const float4*)(W + (long)(col0 + r_st0) * D_ + kq_st0);
    float4 aR1 = *(const float4*)(A + (long)(row0 + r_st1) * D_ + kq_st1);
    float4 wR1 = *(const float4*)(W + (long)(col0 + r_st1) * D_ + kq_st1);
    As[0][kq_st0 + 0][r_st0] = aR0.x; As[0][kq_st0 + 1][r_st0] = aR0.y;
    As[0][kq_st0 + 2][r_st0] = aR0.z; As[0][kq_st0 + 3][r_st0] = aR0.w;
    Ws[0][kq_st0 + 0][r_st0] = wR0.x; Ws[0][kq_st0 + 1][r_st0] = wR0.y;
    Ws[0][kq_st0 + 2][r_st0] = wR0.z; Ws[0][kq_st0 + 3][r_st0] = wR0.w;
    As[0][kq_st1 + 0][r_st1] = aR1.x; As[0][kq_st1 + 1][r_st1] = aR1.y;
    As[0][kq_st1 + 2][r_st1] = aR1.z; As[0][kq_st1 + 3][r_st1] = aR1.w;
    Ws[0][kq_st1 + 0][r_st1] = wR1.x; Ws[0][kq_st1 + 1][r_st1] = wR1.y;
    Ws[0][kq_st1 + 2][r_st1] = wR1.z; Ws[0][kq_st1 + 3][r_st1] = wR1.w;
    aR0 = *(const float4*)(A + (long)(row0 + r_st0) * D_ + 16 + kq_st0);
    wR0 = *(const float4*)(W + (long)(col0 + r_st0) * D_ + 16 + kq_st0);
    aR1 = *(const float4*)(A + (long)(row0 + r_st1) * D_ + 16 + kq_st1);
    wR1 = *(const float4*)(W + (long)(col0 + r_st1) * D_ + 16 + kq_st1);

#pragma unroll 1
    for (int t = 0; t < 32; t++) {
        __syncthreads();   // buf[t&1] visible; all warps done reading buf[(t+1)&1]
        const int nb = (t + 1) & 1;
        if (t + 1 < 32) {  // commit staged regs (tile t+1)
            As[nb][kq_st0 + 0][r_st0] = aR0.x; As[nb][kq_st0 + 1][r_st0] = aR0.y;
            As[nb][kq_st0 + 2][r_st0] = aR0.z; As[nb][kq_st0 + 3][r_st0] = aR0.w;
            Ws[nb][kq_st0 + 0][r_st0] = wR0.x; Ws[nb][kq_st0 + 1][r_st0] = wR0.y;
            Ws[nb][kq_st0 + 2][r_st0] = wR0.z; Ws[nb][kq_st0 + 3][r_st0] = wR0.w;
            As[nb][kq_st1 + 0][r_st1] = aR1.x; As[nb][kq_st1 + 1][r_st1] = aR1.y;
            As[nb][kq_st1 + 2][r_st1] = aR1.z; As[nb][kq_st1 + 3][r_st1] = aR1.w;
            Ws[nb][kq_st1 + 0][r_st1] = wR1.x; Ws[nb][kq_st1 + 1][r_st1] = wR1.y;
            Ws[nb][kq_st1 + 2][r_st1] = wR1.z; Ws[nb][kq_st1 + 3][r_st1] = wR1.w;
        }
        if (t + 2 < 32) {  // LDG tile t+2 (latency hidden under compute below)
            int kn = (t + 2) * 16;
            aR0 = *(const float4*)(A + (long)(row0 + r_st0) * D_ + kn + kq_st0);
            wR0 = *(const float4*)(W + (long)(col0 + r_st0) * D_ + kn + kq_st0);
            aR1 = *(const float4*)(A + (long)(row0 + r_st1) * D_ + kn + kq_st1);
            wR1 = *(const float4*)(W + (long)(col0 + r_st1) * D_ + kn + kq_st1);
        }
        const int cb = t & 1;
#pragma unroll
        for (int k = 0; k < 16; k++) {
            float a[8];
            *(float4*)&a[0] = *(const float4*)&As[cb][k][ty * 8];
            *(float4*)&a[4] = *(const float4*)&As[cb][k][ty * 8 + 4];
            ulonglong2 b01 = *(const ulonglong2*)&Ws[cb][k][tx * 8];
            ulonglong2 b23 = *(const ulonglong2*)&Ws[cb][k][tx * 8 + 4];
            unsigned long long b2[4] = {b01.x, b01.y, b23.x, b23.y};
#pragma unroll
            for (int j = 0; j < 8; j++) {
                unsigned long long aj = bcast2f(a[j]);
                fma2(acc2[j][0], aj, b2[0]);
                fma2(acc2[j][1], aj, b2[1]);
                fma2(acc2[j][2], aj, b2[2]);
                fma2(acc2[j][3], aj, b2[3]);
            }
        }
    }

    float bv[8];
    *(float4*)&bv[0] = *(const float4*)(bias + col0 + tx * 8);
    *(float4*)&bv[4] = *(const float4*)(bias + col0 + tx * 8 + 4);
#pragma unroll
    for (int j = 0; j < 8; j++) {
        int row = row0 + ty * 8 + j;
        float2 c0 = unpack2(acc2[j][0]);
        float2 c1 = unpack2(acc2[j][1]);
        float2 c2 = unpack2(acc2[j][2]);
        float2 c3 = unpack2(acc2[j][3]);
        float4 r0 = make_float4(c0.x + bv[0], c0.y + bv[1],
                                c1.x + bv[2], c1.y + bv[3]);
        float4 r1 = make_float4(c2.x + bv[4], c2.y + bv[5],
                                c3.x + bv[6], c3.y + bv[7]);
        *(float4*)(C + (long)row * D_ + col0 + tx * 8)     = r0;
        *(float4*)(C + (long)row * D_ + col0 + tx * 8 + 4) = r1;
    }
}

// single-output GEMM (used for the Wo projection)
__global__ void __launch_bounds__(256)
gemm_bias_kernel(const float* __restrict__ A, const float* __restrict__ W,
                 const float* __restrict__ bias, float* __restrict__ C)
{
    gemm_body(A, W, bias, C, blockIdx.y << 7, blockIdx.x << 7);
}

// fused QKV: gridDim.z = 3 selects {cur,Wq,bq,Qb} / {agg,Wk,bk,Kb} / {agg,Wv,bv,Vb}.
// One launch => one partial-wave tail instead of three.
__global__ void __launch_bounds__(256)
qkv_gemm_kernel(const float* __restrict__ cur, const float* __restrict__ agg,
                const float* __restrict__ Wq, const float* __restrict__ Wk,
                const float* __restrict__ Wv,
                const float* __restrict__ bq, const float* __restrict__ bk,
                const float* __restrict__ bv,
                float* __restrict__ Qb, float* __restrict__ Kb,
                float* __restrict__ Vb)
{
    const int z = blockIdx.z;
    const float* A    = (z == 0) ? cur : agg;
    const float* W    = (z == 0) ? Wq : (z == 1) ? Wk : Wv;
    const float* bias = (z == 0) ? bq : (z == 1) ? bk : bv;
    float*       C    = (z == 0) ? Qb : (z == 1) ? Kb : Vb;
    gemm_body(A, W, bias, C, blockIdx.y << 7, blockIdx.x << 7);
}

// ---------------- Kernel 3: flash attention, 8-rows-per-warp f32x2 ---------
// grid: (N/64, B*H). block: 256 threads (8 warps). Warp g owns q-rows
// 8g..8g+7 as four packed row-pairs; lane l owns kv cols / out dims (2l,2l+1).
// Per d: 2 lane-uniform LDS.128 (Q row-pairs) + 1 LDS.64 (K) + 2 bcast + 8 fma2
// => FMA-pipe-bound at >=2 warps/SMSP. Dynamic smem (50KB): Qt + (Kt|Ps) + Vs.
__global__ void __launch_bounds__(256)
attn_kernel(const float* __restrict__ Qg, const float* __restrict__ Kg,
            const float* __restrict__ Vg, const float* __restrict__ adj,
            float* __restrict__ Og)
{
    extern __shared__ __align__(16) float smbuf[];
    float* Qt   = smbuf;                              // [64 d][QSTR]
    float* KtPs = smbuf + 64 * QSTR;                  // Kt[d][KSTR] | Ps[c][PSTR]
    float* Vs   = smbuf + 64 * QSTR + 64 * PSTR;      // [c][64]

    const int tid = threadIdx.x;
    const int g = tid >> 5, l = tid & 31;
    const int b = blockIdx.y >> 3, h = blockIdx.y & 7;
    const int q0 = blockIdx.x * QR_;

    const float* Qbase = Qg + ((long)(b * N_ + q0) * D_) + h * HD_;
    // stage Qt transposed + scaled: Qt[d][r] = 0.125 * Q[r][d], 64 rows
#pragma unroll
    for (int j = 0; j < 4; j++) {
        int fi = tid + j * 256;          // 0..1023 = 64 rows x 16 float4
        int r = fi >> 4, f4 = (fi & 15) * 4;
        float4 q = *(const float4*)(Qbase + (long)r * D_ + f4);
        Qt[(f4 + 0) * QSTR + r] = q.x * 0.125f;
        Qt[(f4 + 1) * QSTR + r] = q.y * 0.125f;
        Qt[(f4 + 2) * QSTR + r] = q.z * 0.125f;
        Qt[(f4 + 3) * QSTR + r] = q.w * 0.125f;
    }

    // o2[p][dd]: packed {o[8g+2p][2l+dd], o[8g+2p+1][2l+dd]}
    unsigned long long o2[4][2] = {{0ull,0ull},{0ull,0ull},{0ull,0ull},{0ull,0ull}};
    float mrow[8], lsum[8];
#pragma unroll
    for (int r = 0; r < 8; r++) { mrow[r] = -1e30f; lsum[r] = 0.f; }

#pragma unroll 1
    for (int t = 0; t < 16; t++) {
        const int c0 = t * 64;
        __syncthreads();   // prev PV done reading Ps/Vs (and Qt staged, iter 0)

        const float* Kbase = Kg + ((long)(b * N_ + c0) * D_) + h * HD_;
        const float* Vbase = Vg + ((long)(b * N_ + c0) * D_) + h * HD_;
#pragma unroll
        for (int j = 0; j < 4; j++) {
            int fi = tid + j * 256;      // 64 rows x 16 float4
            int c = fi >> 4, f4 = (fi & 15) * 4;
            float4 kv = *(const float4*)(Kbase + (long)c * D_ + f4);
            KtPs[(f4 + 0) * KSTR + c] = kv.x;
            KtPs[(f4 + 1) * KSTR + c] = kv.y;
            KtPs[(f4 + 2) * KSTR + c] = kv.z;
            KtPs[(f4 + 3) * KSTR + c] = kv.w;
            float4 vv = *(const float4*)(Vbase + (long)c * D_ + f4);
            *(float4*)&Vs[c * 64 + f4] = vv;
        }
        __syncthreads();

        // adjacency bias prefetch (L2-resident), 8 rows
        float2 ad[8];
#pragma unroll
        for (int rr = 0; rr < 8; rr++)
            ad[rr] = *(const float2*)(adj + (long)(q0 + 8 * g + rr) * N_ + c0 + 2 * l);

        // QK^T: s2[p][cc] = {s[8g+2p][2l+cc], s[8g+2p+1][2l+cc]}
        unsigned long long s2[4][2] = {{0ull,0ull},{0ull,0ull},{0ull,0ull},{0ull,0ull}};
#pragma unroll
        for (int d = 0; d < 64; d++) {
            ulonglong2 qA = *(const ulonglong2*)&Qt[d * QSTR + 8 * g];      // rows 8g..+3
            ulonglong2 qB = *(const ulonglong2*)&Qt[d * QSTR + 8 * g + 4];  // rows +4..+7
            float2 kk = *(const float2*)&KtPs[d * KSTR + 2 * l];
            unsigned long long k0 = bcast2f(kk.x);
            unsigned long long k1 = bcast2f(kk.y);
            fma2(s2[0][0], qA.x, k0); fma2(s2[0][1], qA.x, k1);
            fma2(s2[1][0], qA.y, k0); fma2(s2[1][1], qA.y, k1);
            fma2(s2[2][0], qB.x, k0); fma2(s2[2][1], qB.x, k1);
            fma2(s2[3][0], qB.y, k0); fma2(s2[3][1], qB.y, k1);
        }
        __syncthreads();   // all warps done with Kt before Ps overlays it

        // unpack scores into per-row scalars
        float x0[8], x1[8];
#pragma unroll
        for (int p = 0; p < 4; p++) {
            float2 sa = unpack2(s2[p][0]);   // col 2l:   {row 8g+2p, row 8g+2p+1}
            float2 sb = unpack2(s2[p][1]);   // col 2l+1
            x0[2 * p] = sa.x;     x1[2 * p] = sb.x;
            x0[2 * p + 1] = sa.y; x1[2 * p + 1] = sb.y;
        }
        float pr0[8], pr1[8], alv[8];
#pragma unroll
        for (int rr = 0; rr < 8; rr++) {
            float v0 = fmaf(ad[rr].x, 0.5f, x0[rr]);
            float v1 = fmaf(ad[rr].y, 0.5f, x1[rr]);
            float mx = warpMax(fmaxf(v0, v1));
            float mn = fmaxf(mrow[rr], mx);
            float al = __expf(mrow[rr] - mn);
            mrow[rr] = mn;
            float p0 = __expf(v0 - mn);
            float p1 = __expf(v1 - mn);
            float ps = warpSum(p0 + p1);
            lsum[rr] = lsum[rr] * al + ps;
            alv[rr] = al; pr0[rr] = p0; pr1[rr] = p1;
        }
        // rescale packed outputs: pair p scales by {alv[2p], alv[2p+1]}
#pragma unroll
        for (int p = 0; p < 4; p++) {
            unsigned long long ap = pack2f(alv[2 * p], alv[2 * p + 1]);
            mul2(o2[p][0], ap); mul2(o2[p][1], ap);
        }
        // stage Ps[c][r] (transposed, stride PSTR): col 2l <- pr0, col 2l+1 <- pr1
#pragma unroll
        for (int p = 0; p < 4; p++) {
            *(float2*)&KtPs[(2 * l) * PSTR + 8 * g + 2 * p]     = make_float2(pr0[2 * p], pr0[2 * p + 1]);
            *(float2*)&KtPs[(2 * l + 1) * PSTR + 8 * g + 2 * p] = make_float2(pr1[2 * p], pr1[2 * p + 1]);
        }
        __syncwarp();      // warp g only reads rows 8g..8g+7 (its own writes)

        // PV: o2[p][dd] += {P[8g+2p][c], P[8g+2p+1][c]} * V[c][2l+dd]
#pragma unroll
        for (int c = 0; c < 64; c++) {
            ulonglong2 pA = *(const ulonglong2*)&KtPs[c * PSTR + 8 * g];
            ulonglong2 pB = *(const ulonglong2*)&KtPs[c * PSTR + 8 * g + 4];
            float2 vv = *(const float2*)&Vs[c * 64 + 2 * l];
            unsigned long long v0 = bcast2f(vv.x);
            unsigned long long v1 = bcast2f(vv.y);
            fma2(o2[0][0], pA.x, v0); fma2(o2[0][1], pA.x, v1);
            fma2(o2[1][0], pA.y, v0); fma2(o2[1][1], pA.y, v1);
            fma2(o2[2][0], pB.x, v0); fma2(o2[2][1], pB.x, v1);
            fma2(o2[3][0], pB.y, v0); fma2(o2[3][1], pB.y, v1);
        }
    }

    // epilogue: unpack row pairs, normalize, store
#pragma unroll
    for (int p = 0; p < 4; p++) {
        float2 oa = unpack2(o2[p][0]);   // {o[re][2l],   o[ro][2l]}
        float2 ob = unpack2(o2[p][1]);   // {o[re][2l+1], o[ro][2l+1]}
        float ie = 1.f / lsum[2 * p];
        float io = 1.f / lsum[2 * p + 1];
        int re = q0 + 8 * g + 2 * p;
        *(float2*)(Og + ((long)(b * N_ + re) * D_) + h * HD_ + 2 * l)
            = make_float2(oa.x * ie, ob.x * ie);
        *(float2*)(Og + ((long)(b * N_ + re + 1) * D_) + h * HD_ + 2 * l)
            = make_float2(oa.y * io, ob.y * io);
    }
}

// ---------------- Kernel 4: residual + LayerNorm ---------------------------
__global__ void __launch_bounds__(128)
ln_kernel(const float* __restrict__ cur, const float* __restrict__ O,
          const float* __restrict__ gg, const float* __restrict__ bb,
          float* __restrict__ outp)
{
    __shared__ float red[8];
    const int row = blockIdx.x;
    const int t = threadIdx.x;
    const long base = (long)row * D_ + t * 4;

    float4 c4 = *(const float4*)(cur + base);
    float4 o4 = *(const float4*)(O + base);
    float4 x = make_float4(c4.x + o4.x, c4.y + o4.y, c4.z + o4.z, c4.w + o4.w);

    float s = x.x + x.y + x.z + x.w;
    float q = x.x * x.x + x.y * x.y + x.z * x.z + x.w * x.w;
    s = warpSum(s);
    q = warpSum(q);
    int wid = t >> 5;
    if ((t & 31) == 0) { red[wid] = s; red[4 + wid] = q; }
    __syncthreads();
    s = red[0] + red[1] + red[2] + red[3];
    q = red[4] + red[5] + red[6] + red[7];

    float mu = s * (1.f / D_);
    float var = q * (1.f / D_) - mu * mu;
    float rs = rsqrtf(var + 1e-5f);

    float4 g4 = *(const float4*)(gg + t * 4);
    float4 b4 = *(const float4*)(bb + t * 4);
    float4 y;
    y.x = (x.x - mu) * rs * g4.x + b4.x;
    y.y = (x.y - mu) * rs * g4.y + b4.y;
    y.z = (x.z - mu) * rs * g4.z + b4.z;
    y.w = (x.w - mu) * rs * g4.w + b4.w;
    *(float4*)(outp + base) = y;
}

// ---------------- launcher -------------------------------------------------
extern "C" void kernel_launch(void* const* d_in, const int* in_sizes, int n_in,
                              void* d_out, int out_size)
{
    const float* cur  = (const float*)d_in[0];
    const float* lf   = (const float*)d_in[1];
    const float* lw   = (const float*)d_in[2];
    const float* Wq   = (const float*)d_in[3];
    const float* bq   = (const float*)d_in[4];
    const float* Wk   = (const float*)d_in[5];
    const float* bk   = (const float*)d_in[6];
    const float* Wv   = (const float*)d_in[7];
    const float* bv   = (const float*)d_in[8];
    const float* Wo   = (const float*)d_in[9];
    const float* bo   = (const float*)d_in[10];
    const float* adj  = (const float*)d_in[11];
    const float* lng  = (const float*)d_in[12];
    const float* lnb  = (const float*)d_in[13];
    float* outp = (float*)d_out;

    float *agg, *Qb, *Kb, *Vb, *Ab, *Ob;
    cudaGetSymbolAddress((void**)&agg, g_agg);
    cudaGetSymbolAddress((void**)&Qb,  g_Qb);
    cudaGetSymbolAddress((void**)&Kb,  g_Kb);
    cudaGetSymbolAddress((void**)&Vb,  g_Vb);
    cudaGetSymbolAddress((void**)&Ab,  g_att);
    cudaGetSymbolAddress((void**)&Ob,  g_Ob);

    // opt-in >48KB dynamic smem for attention (sticky per-function attribute;
    // runs immediately, not a stream op, so it is graph-capture-safe)
    cudaFuncSetAttribute(attn_kernel,
                         cudaFuncAttributeMaxDynamicSharedMemorySize,
                         ATTN_SMEM_BYTES);

    // 1) lag-weighted aggregation
    lag_agg_kernel<<<(BN_ * D_ / 4) / 256, 256>>>(lf, lw, agg);

    // 2) fused Q,K,V projections (one launch, one tail wave)
    dim3 qkvgrid(D_ / 128, BN_ / 128, 3);
    qkv_gemm_kernel<<<qkvgrid, 256>>>(cur, agg, Wq, Wk, Wv, bq, bk, bv,
                                      Qb, Kb, Vb);

    // 3) attention with adjacency bias
    dim3 agrid(N_ / QR_, B_ * H_);
    attn_kernel<<<agrid, 256, ATTN_SMEM_BYTES>>>(Qb, Kb, Vb, adj, Ab);

    // 4) output projection
    dim3 ggrid(D_ / 128, BN_ / 128);
    gemm_bias_kernel<<<ggrid, 256>>>(Ab, Wo, bo, Ob);

    // 5) residual + layernorm
    ln_kernel<<<BN_, 128>>>(cur, Ob, lng, lnb, outp);
}